// round 9
// baseline (speedup 1.0000x reference)
#include <cuda_runtime.h>
#include <cstdint>
#include <math.h>

// x [128, 1, 512, 512] fp32.
//   pred = softplus(x); m = max over sample; out = (m > 1e-8) ? pred/m : pred.
// softplus monotone => m = softplus(max(x)).
//
// R9 = R8 + (a) 4 slices of 32 samples (33.5 MB — kills the residual ~14 MB
// per-slice L2 misses R8 measured) and (b) software-pipelined K2: all 8
// float4 loads issued before any compute (R8's K2 showed DRAM 53%/issue 25%
// = latency-exposed at 4 loads in flight).

#define SAMPLES 128
#define SLICES 4
#define SAMPLES_PER_SLICE (SAMPLES / SLICES)     // 32
#define SAMPLE_ELEMS (512 * 512)                 // 262144
#define SAMPLE_N4 (SAMPLE_ELEMS / 4)             // 65536 float4
#define CHUNKS 32                                // CTAs per sample
#define CHUNK_N4 (SAMPLE_N4 / CHUNKS)            // 2048 float4 per CTA
#define SLICE_BLOCKS (SAMPLES_PER_SLICE * CHUNKS)  // 1024
#define THREADS 256                              // 8 float4 per thread
#define EPS 1e-8f
#define LOG2E 1.4426950408889634f
#define LN2   0.6931471805599453f

__device__ float g_partial[SAMPLES * CHUNKS];    // written every call before read

__device__ __forceinline__ float softplus_accurate(float x) {
    return fmaxf(x, 0.0f) + log1pf(__expf(-fabsf(x)));
}

__device__ __forceinline__ float ex2f(float x) {
    float r; asm("ex2.approx.ftz.f32 %0, %1;" : "=f"(r) : "f"(x)); return r;
}
__device__ __forceinline__ float lg2f(float x) {
    float r; asm("lg2.approx.ftz.f32 %0, %1;" : "=f"(r) : "f"(x)); return r;
}

// out = softplus(x) * scale, fast MUFU path (2 MUFU + ~5 alu/fma).
__device__ __forceinline__ float softplus_scaled(float x, float scale, float scale_ln2) {
    float t = ex2f(-LOG2E * fabsf(x));           // e^(-|x|)
    float l = lg2f(1.0f + t);                    // log2(1 + e^-|x|)
    return fmaf(scale, fmaxf(x, 0.0f), scale_ln2 * l);
}

// ---------- K1: per-chunk max over one slice ----------
__global__ __launch_bounds__(THREADS)
void max_kernel(const float* __restrict__ x_slice, float* __restrict__ partial_slice) {
    const float4* __restrict__ xin =
        reinterpret_cast<const float4*>(x_slice) + (size_t)blockIdx.x * CHUNK_N4;
    const int tid = threadIdx.x;

    float m0 = -INFINITY, m1 = -INFINITY, m2 = -INFINITY, m3 = -INFINITY;
    #pragma unroll
    for (int it = 0; it < 2; it++) {
        int base = it * 4 * THREADS + tid;
        float4 a = xin[base];
        float4 b = xin[base + THREADS];
        float4 c = xin[base + 2 * THREADS];
        float4 d = xin[base + 3 * THREADS];
        m0 = fmaxf(m0, fmaxf(fmaxf(a.x, a.y), fmaxf(a.z, a.w)));
        m1 = fmaxf(m1, fmaxf(fmaxf(b.x, b.y), fmaxf(b.z, b.w)));
        m2 = fmaxf(m2, fmaxf(fmaxf(c.x, c.y), fmaxf(c.z, c.w)));
        m3 = fmaxf(m3, fmaxf(fmaxf(d.x, d.y), fmaxf(d.z, d.w)));
    }
    float m = fmaxf(fmaxf(m0, m1), fmaxf(m2, m3));

    #pragma unroll
    for (int off = 16; off; off >>= 1)
        m = fmaxf(m, __shfl_xor_sync(0xFFFFFFFFu, m, off));

    __shared__ float red[THREADS / 32];
    if ((tid & 31) == 0) red[tid >> 5] = m;
    __syncthreads();
    if (tid < (THREADS / 32)) {
        float v = red[tid];
        #pragma unroll
        for (int off = (THREADS / 64); off; off >>= 1)
            v = fmaxf(v, __shfl_xor_sync(0xFFFFFFFFu, v, off));
        if (tid == 0) partial_slice[blockIdx.x] = v;   // distinct slot, no atomic
    }
}

// ---------- K2: reduce partials + normalize one slice ----------
__global__ __launch_bounds__(THREADS)
void norm_kernel(const float* __restrict__ x_slice, float* __restrict__ out_slice,
                 const float* __restrict__ partial_slice) {
    const int sample = blockIdx.x >> 5;              // / CHUNKS (within slice)
    const size_t off4 = (size_t)blockIdx.x * CHUNK_N4;
    const float4* __restrict__ xin = reinterpret_cast<const float4*>(x_slice) + off4;
    float4* __restrict__ o = reinterpret_cast<float4*>(out_slice) + off4;
    const int tid = threadIdx.x;

    __shared__ float s_scale;
    if (tid < 32) {
        float v = partial_slice[sample * CHUNKS + tid];  // CHUNKS == 32
        #pragma unroll
        for (int off = 16; off; off >>= 1)
            v = fmaxf(v, __shfl_xor_sync(0xFFFFFFFFu, v, off));
        if (tid == 0) {
            float sm = softplus_accurate(v);   // = max(softplus(x)), monotone
            s_scale = (sm > EPS) ? (1.0f / sm) : 1.0f;
        }
    }
    __syncthreads();
    const float scale = s_scale;
    const float scale_ln2 = scale * LN2;

    // Software pipeline: all 8 loads in flight before any dependent compute.
    float4 v[8];
    #pragma unroll
    for (int i = 0; i < 8; i++)
        v[i] = __ldcs(&xin[i * THREADS + tid]);

    #pragma unroll
    for (int i = 0; i < 8; i++) {
        float4 r;
        r.x = softplus_scaled(v[i].x, scale, scale_ln2);
        r.y = softplus_scaled(v[i].y, scale, scale_ln2);
        r.z = softplus_scaled(v[i].z, scale, scale_ln2);
        r.w = softplus_scaled(v[i].w, scale, scale_ln2);
        __stcs(&o[i * THREADS + tid], r);
    }
}

extern "C" void kernel_launch(void* const* d_in, const int* in_sizes, int n_in,
                              void* d_out, int out_size) {
    const float* x = (const float*)d_in[0];
    float* out = (float*)d_out;

    float* g_partial_ptr = nullptr;
    cudaGetSymbolAddress((void**)&g_partial_ptr, g_partial);

    const size_t slice_elems = (size_t)SAMPLES_PER_SLICE * SAMPLE_ELEMS;
    for (int s = 0; s < SLICES; s++) {
        const float* xs = x + s * slice_elems;
        float* os = out + s * slice_elems;
        float* ps = g_partial_ptr + s * SLICE_BLOCKS;
        max_kernel<<<SLICE_BLOCKS, THREADS>>>(xs, ps);
        norm_kernel<<<SLICE_BLOCKS, THREADS>>>(xs, os, ps);
    }
}

// round 10
// speedup vs baseline: 1.1410x; 1.1410x over previous
#include <cuda_runtime.h>
#include <cstdint>
#include <math.h>

// x [128, 1, 512, 512] fp32.
//   pred = softplus(x); m = max over sample; out = (m > 1e-8) ? pred/m : pred.
// softplus monotone => m = softplus(max(x)).
//
// R10: 4 slices of 32 samples (33.5 MB, L2-resident), software-pipelined
// across launches by ROLE MIXING: each middle launch runs K2(slice s) on even
// blocks and K1(slice s+1) on odd blocks, so DRAM reads and writes overlap
// within the launch. K2 body reverted to R8's 4-deep / 32-reg form (R9's
// 8-deep batch cost occupancy 76->47% and 1.5 TB/s).
// Launches: K1(0) | K2(0)+K1(1) | K2(1)+K1(2) | K2(2)+K1(3) | K2(3).

#define SAMPLES 128
#define SLICES 4
#define SAMPLES_PER_SLICE (SAMPLES / SLICES)       // 32
#define SAMPLE_ELEMS (512 * 512)                   // 262144
#define SAMPLE_N4 (SAMPLE_ELEMS / 4)               // 65536 float4
#define CHUNKS 32                                  // chunk-CTAs per sample
#define CHUNK_N4 (SAMPLE_N4 / CHUNKS)              // 2048 float4 per chunk
#define SLICE_BLOCKS (SAMPLES_PER_SLICE * CHUNKS)  // 1024 chunks per slice
#define THREADS 256                                // 8 float4 per thread
#define EPS 1e-8f
#define LOG2E 1.4426950408889634f
#define LN2   0.6931471805599453f

__device__ float g_partial[SAMPLES * CHUNKS];      // written every call before read

__device__ __forceinline__ float softplus_accurate(float x) {
    return fmaxf(x, 0.0f) + log1pf(__expf(-fabsf(x)));
}

__device__ __forceinline__ float ex2f(float x) {
    float r; asm("ex2.approx.ftz.f32 %0, %1;" : "=f"(r) : "f"(x)); return r;
}
__device__ __forceinline__ float lg2f(float x) {
    float r; asm("lg2.approx.ftz.f32 %0, %1;" : "=f"(r) : "f"(x)); return r;
}

// out = softplus(x) * scale, fast MUFU path (2 MUFU + ~5 alu/fma).
__device__ __forceinline__ float softplus_scaled(float x, float scale, float scale_ln2) {
    float t = ex2f(-LOG2E * fabsf(x));             // e^(-|x|)
    float l = lg2f(1.0f + t);                      // log2(1 + e^-|x|)
    return fmaf(scale, fmaxf(x, 0.0f), scale_ln2 * l);
}

// mode: 0 = mixed (even blocks K2, odd blocks K1), 1 = K1 only, 2 = K2 only.
__global__ __launch_bounds__(THREADS)
void pipe_kernel(const float* __restrict__ x1, float* __restrict__ part1,
                 const float* __restrict__ x2, float* __restrict__ out2,
                 const float* __restrict__ part2,
                 int mode) {
    int is_k1, cid;
    if (mode == 0)      { is_k1 = blockIdx.x & 1; cid = blockIdx.x >> 1; }
    else if (mode == 1) { is_k1 = 1; cid = blockIdx.x; }
    else                { is_k1 = 0; cid = blockIdx.x; }

    const int tid = threadIdx.x;
    __shared__ float s_red[THREADS / 32];
    __shared__ float s_scale;

    if (is_k1) {
        // -------- K1: max over chunk cid of slice x1 (default loads: fill L2) --------
        const float4* __restrict__ xin =
            reinterpret_cast<const float4*>(x1) + (size_t)cid * CHUNK_N4;

        float m0 = -INFINITY, m1 = -INFINITY, m2 = -INFINITY, m3 = -INFINITY;
        #pragma unroll
        for (int it = 0; it < 2; it++) {
            int base = it * 4 * THREADS + tid;
            float4 a = xin[base];
            float4 b = xin[base + THREADS];
            float4 c = xin[base + 2 * THREADS];
            float4 d = xin[base + 3 * THREADS];
            m0 = fmaxf(m0, fmaxf(fmaxf(a.x, a.y), fmaxf(a.z, a.w)));
            m1 = fmaxf(m1, fmaxf(fmaxf(b.x, b.y), fmaxf(b.z, b.w)));
            m2 = fmaxf(m2, fmaxf(fmaxf(c.x, c.y), fmaxf(c.z, c.w)));
            m3 = fmaxf(m3, fmaxf(fmaxf(d.x, d.y), fmaxf(d.z, d.w)));
        }
        float m = fmaxf(fmaxf(m0, m1), fmaxf(m2, m3));

        #pragma unroll
        for (int off = 16; off; off >>= 1)
            m = fmaxf(m, __shfl_xor_sync(0xFFFFFFFFu, m, off));
        if ((tid & 31) == 0) s_red[tid >> 5] = m;
        __syncthreads();
        if (tid < (THREADS / 32)) {
            float v = s_red[tid];
            #pragma unroll
            for (int off = (THREADS / 64); off; off >>= 1)
                v = fmaxf(v, __shfl_xor_sync(0xFFFFFFFFu, v, off));
            if (tid == 0) part1[cid] = v;          // distinct slot, no atomic
        }
    } else {
        // -------- K2: normalize chunk cid of slice x2 (reads hit L2) --------
        const int sample = cid >> 5;               // / CHUNKS (within slice)
        const size_t off4 = (size_t)cid * CHUNK_N4;
        const float4* __restrict__ xin = reinterpret_cast<const float4*>(x2) + off4;
        float4* __restrict__ o = reinterpret_cast<float4*>(out2) + off4;

        if (tid < 32) {
            float v = part2[sample * CHUNKS + tid];    // CHUNKS == 32
            #pragma unroll
            for (int off = 16; off; off >>= 1)
                v = fmaxf(v, __shfl_xor_sync(0xFFFFFFFFu, v, off));
            if (tid == 0) {
                float sm = softplus_accurate(v);   // = max(softplus(x)), monotone
                s_scale = (sm > EPS) ? (1.0f / sm) : 1.0f;
            }
        }
        __syncthreads();
        const float scale = s_scale;
        const float scale_ln2 = scale * LN2;

        #pragma unroll
        for (int it = 0; it < 2; it++) {
            int base = it * 4 * THREADS + tid;
            float4 a = __ldcs(&xin[base]);
            float4 b = __ldcs(&xin[base + THREADS]);
            float4 c = __ldcs(&xin[base + 2 * THREADS]);
            float4 d = __ldcs(&xin[base + 3 * THREADS]);
            float4 ra, rb, rc, rd;
            ra.x = softplus_scaled(a.x, scale, scale_ln2);
            ra.y = softplus_scaled(a.y, scale, scale_ln2);
            ra.z = softplus_scaled(a.z, scale, scale_ln2);
            ra.w = softplus_scaled(a.w, scale, scale_ln2);
            rb.x = softplus_scaled(b.x, scale, scale_ln2);
            rb.y = softplus_scaled(b.y, scale, scale_ln2);
            rb.z = softplus_scaled(b.z, scale, scale_ln2);
            rb.w = softplus_scaled(b.w, scale, scale_ln2);
            rc.x = softplus_scaled(c.x, scale, scale_ln2);
            rc.y = softplus_scaled(c.y, scale, scale_ln2);
            rc.z = softplus_scaled(c.z, scale, scale_ln2);
            rc.w = softplus_scaled(c.w, scale, scale_ln2);
            rd.x = softplus_scaled(d.x, scale, scale_ln2);
            rd.y = softplus_scaled(d.y, scale, scale_ln2);
            rd.z = softplus_scaled(d.z, scale, scale_ln2);
            rd.w = softplus_scaled(d.w, scale, scale_ln2);
            __stcs(&o[base], ra);
            __stcs(&o[base + THREADS], rb);
            __stcs(&o[base + 2 * THREADS], rc);
            __stcs(&o[base + 3 * THREADS], rd);
        }
    }
}

extern "C" void kernel_launch(void* const* d_in, const int* in_sizes, int n_in,
                              void* d_out, int out_size) {
    const float* x = (const float*)d_in[0];
    float* out = (float*)d_out;

    float* gp = nullptr;
    cudaGetSymbolAddress((void**)&gp, g_partial);

    const size_t se = (size_t)SAMPLES_PER_SLICE * SAMPLE_ELEMS;

    // Prologue: K1 on slice 0.
    pipe_kernel<<<SLICE_BLOCKS, THREADS>>>(
        x, gp, nullptr, nullptr, nullptr, 1);

    // Middle: K2(s-1) interleaved with K1(s).
    for (int s = 1; s < SLICES; s++) {
        pipe_kernel<<<2 * SLICE_BLOCKS, THREADS>>>(
            x + s * se, gp + s * SLICE_BLOCKS,
            x + (s - 1) * se, out + (s - 1) * se, gp + (s - 1) * SLICE_BLOCKS,
            0);
    }

    // Epilogue: K2 on the last slice.
    pipe_kernel<<<SLICE_BLOCKS, THREADS>>>(
        nullptr, nullptr,
        x + (SLICES - 1) * se, out + (SLICES - 1) * se,
        gp + (SLICES - 1) * SLICE_BLOCKS, 2);
}

// round 11
// speedup vs baseline: 1.1423x; 1.0011x over previous
#include <cuda_runtime.h>
#include <cstdint>
#include <math.h>

// x [128, 1, 512, 512] fp32.
//   pred = softplus(x); m = max over sample; out = (m > 1e-8) ? pred/m : pred.
// softplus monotone => m = softplus(max(x)).
//
// R11 = R10 pipeline + finer CTA granularity.
// R10's mixed launches ran 2.1 waves of ~7.5us CTAs -> multi-us tail per
// launch (DRAM 56% despite traffic at the 268 MB floor). Halve the chunk
// (CHUNKS 64, 1024 float4 per CTA, 4 float4/thread): 2x CTAs per launch at
// half the duration => ~4.3 waves, tail cost halved.
// Launches: K1(0) | K2(0)+K1(1) | K2(1)+K1(2) | K2(2)+K1(3) | K2(3).

#define SAMPLES 128
#define SLICES 4
#define SAMPLES_PER_SLICE (SAMPLES / SLICES)       // 32
#define SAMPLE_ELEMS (512 * 512)                   // 262144
#define SAMPLE_N4 (SAMPLE_ELEMS / 4)               // 65536 float4
#define CHUNKS 64                                  // chunk-CTAs per sample
#define CHUNK_N4 (SAMPLE_N4 / CHUNKS)              // 1024 float4 per chunk
#define SLICE_BLOCKS (SAMPLES_PER_SLICE * CHUNKS)  // 2048 chunks per slice
#define THREADS 256                                // 4 float4 per thread
#define EPS 1e-8f
#define LOG2E 1.4426950408889634f
#define LN2   0.6931471805599453f

__device__ float g_partial[SAMPLES * CHUNKS];      // written every call before read

__device__ __forceinline__ float softplus_accurate(float x) {
    return fmaxf(x, 0.0f) + log1pf(__expf(-fabsf(x)));
}

__device__ __forceinline__ float ex2f(float x) {
    float r; asm("ex2.approx.ftz.f32 %0, %1;" : "=f"(r) : "f"(x)); return r;
}
__device__ __forceinline__ float lg2f(float x) {
    float r; asm("lg2.approx.ftz.f32 %0, %1;" : "=f"(r) : "f"(x)); return r;
}

// out = softplus(x) * scale, fast MUFU path (2 MUFU + ~5 alu/fma).
__device__ __forceinline__ float softplus_scaled(float x, float scale, float scale_ln2) {
    float t = ex2f(-LOG2E * fabsf(x));             // e^(-|x|)
    float l = lg2f(1.0f + t);                      // log2(1 + e^-|x|)
    return fmaf(scale, fmaxf(x, 0.0f), scale_ln2 * l);
}

// mode: 0 = mixed (even blocks K2, odd blocks K1), 1 = K1 only, 2 = K2 only.
__global__ __launch_bounds__(THREADS)
void pipe_kernel(const float* __restrict__ x1, float* __restrict__ part1,
                 const float* __restrict__ x2, float* __restrict__ out2,
                 const float* __restrict__ part2,
                 int mode) {
    int is_k1, cid;
    if (mode == 0)      { is_k1 = blockIdx.x & 1; cid = blockIdx.x >> 1; }
    else if (mode == 1) { is_k1 = 1; cid = blockIdx.x; }
    else                { is_k1 = 0; cid = blockIdx.x; }

    const int tid = threadIdx.x;
    __shared__ float s_red[THREADS / 32];
    __shared__ float s_scale;

    if (is_k1) {
        // -------- K1: max over chunk cid of slice x1 (default loads: fill L2) --------
        const float4* __restrict__ xin =
            reinterpret_cast<const float4*>(x1) + (size_t)cid * CHUNK_N4;

        float4 a = xin[tid];
        float4 b = xin[tid + THREADS];
        float4 c = xin[tid + 2 * THREADS];
        float4 d = xin[tid + 3 * THREADS];
        float m0 = fmaxf(fmaxf(a.x, a.y), fmaxf(a.z, a.w));
        float m1 = fmaxf(fmaxf(b.x, b.y), fmaxf(b.z, b.w));
        float m2 = fmaxf(fmaxf(c.x, c.y), fmaxf(c.z, c.w));
        float m3 = fmaxf(fmaxf(d.x, d.y), fmaxf(d.z, d.w));
        float m = fmaxf(fmaxf(m0, m1), fmaxf(m2, m3));

        #pragma unroll
        for (int off = 16; off; off >>= 1)
            m = fmaxf(m, __shfl_xor_sync(0xFFFFFFFFu, m, off));
        if ((tid & 31) == 0) s_red[tid >> 5] = m;
        __syncthreads();
        if (tid < (THREADS / 32)) {
            float v = s_red[tid];
            #pragma unroll
            for (int off = (THREADS / 64); off; off >>= 1)
                v = fmaxf(v, __shfl_xor_sync(0xFFFFFFFFu, v, off));
            if (tid == 0) part1[cid] = v;          // distinct slot, no atomic
        }
    } else {
        // -------- K2: normalize chunk cid of slice x2 (reads hit L2) --------
        const int sample = cid / CHUNKS;           // within slice
        const size_t off4 = (size_t)cid * CHUNK_N4;
        const float4* __restrict__ xin = reinterpret_cast<const float4*>(x2) + off4;
        float4* __restrict__ o = reinterpret_cast<float4*>(out2) + off4;

        // Reduce 64 partials with 2 warps, combine via s_red.
        if (tid < CHUNKS) {
            float v = part2[sample * CHUNKS + tid];
            #pragma unroll
            for (int off = 16; off; off >>= 1)
                v = fmaxf(v, __shfl_xor_sync(0xFFFFFFFFu, v, off));
            if ((tid & 31) == 0) s_red[tid >> 5] = v;
        }
        __syncthreads();
        if (tid == 0) {
            float v = fmaxf(s_red[0], s_red[1]);
            float sm = softplus_accurate(v);       // = max(softplus(x)), monotone
            s_scale = (sm > EPS) ? (1.0f / sm) : 1.0f;
        }
        __syncthreads();
        const float scale = s_scale;
        const float scale_ln2 = scale * LN2;

        float4 a = __ldcs(&xin[tid]);
        float4 b = __ldcs(&xin[tid + THREADS]);
        float4 c = __ldcs(&xin[tid + 2 * THREADS]);
        float4 d = __ldcs(&xin[tid + 3 * THREADS]);
        float4 ra, rb, rc, rd;
        ra.x = softplus_scaled(a.x, scale, scale_ln2);
        ra.y = softplus_scaled(a.y, scale, scale_ln2);
        ra.z = softplus_scaled(a.z, scale, scale_ln2);
        ra.w = softplus_scaled(a.w, scale, scale_ln2);
        rb.x = softplus_scaled(b.x, scale, scale_ln2);
        rb.y = softplus_scaled(b.y, scale, scale_ln2);
        rb.z = softplus_scaled(b.z, scale, scale_ln2);
        rb.w = softplus_scaled(b.w, scale, scale_ln2);
        rc.x = softplus_scaled(c.x, scale, scale_ln2);
        rc.y = softplus_scaled(c.y, scale, scale_ln2);
        rc.z = softplus_scaled(c.z, scale, scale_ln2);
        rc.w = softplus_scaled(c.w, scale, scale_ln2);
        rd.x = softplus_scaled(d.x, scale, scale_ln2);
        rd.y = softplus_scaled(d.y, scale, scale_ln2);
        rd.z = softplus_scaled(d.z, scale, scale_ln2);
        rd.w = softplus_scaled(d.w, scale, scale_ln2);
        __stcs(&o[tid], ra);
        __stcs(&o[tid + THREADS], rb);
        __stcs(&o[tid + 2 * THREADS], rc);
        __stcs(&o[tid + 3 * THREADS], rd);
    }
}

extern "C" void kernel_launch(void* const* d_in, const int* in_sizes, int n_in,
                              void* d_out, int out_size) {
    const float* x = (const float*)d_in[0];
    float* out = (float*)d_out;

    float* gp = nullptr;
    cudaGetSymbolAddress((void**)&gp, g_partial);

    const size_t se = (size_t)SAMPLES_PER_SLICE * SAMPLE_ELEMS;

    // Prologue: K1 on slice 0.
    pipe_kernel<<<SLICE_BLOCKS, THREADS>>>(
        x, gp, nullptr, nullptr, nullptr, 1);

    // Middle: K2(s-1) interleaved with K1(s).
    for (int s = 1; s < SLICES; s++) {
        pipe_kernel<<<2 * SLICE_BLOCKS, THREADS>>>(
            x + s * se, gp + s * SLICE_BLOCKS,
            x + (s - 1) * se, out + (s - 1) * se, gp + (s - 1) * SLICE_BLOCKS,
            0);
    }

    // Epilogue: K2 on the last slice.
    pipe_kernel<<<SLICE_BLOCKS, THREADS>>>(
        nullptr, nullptr,
        x + (SLICES - 1) * se, out + (SLICES - 1) * se,
        gp + (SLICES - 1) * SLICE_BLOCKS, 2);
}